// round 7
// baseline (speedup 1.0000x reference)
#include <cuda_runtime.h>
#include <cuda_fp16.h>
#include <math.h>
#include <stdint.h>

#define BB 4096
#define TT 200
#define CC 16
#define HH 112
#define GG 448

#define NSTAT_BLK 256
#define STAT_THREADS 256

#define MB 32            // batch rows per CTA
#define TPB 512          // 16 warps: wm = warp>>3 (m-tile), wn = warp&7 (7 n-tiles)
#define NCTA (BB/MB)     // 128
#define KT_H 7           // k16-tiles for h (112)
#define ABUF (2 * KT_H * 128)   // words per A buffer (1792)

// ---------------- device scratch ----------------
__device__ float g_part[NSTAT_BLK * 32];
__device__ uint2 g_Wfrag_h[56 * KT_H * 32];   // 100,352 B
__device__ uint2 g_Wfrag_x[56 * 32];          // 14,336 B (BN-folded)
__device__ float g_bias_n[GG];                // bias per col n (n = j*4 + gate)

// ---------------- helpers ----------------
static __device__ __forceinline__ uint32_t pkh(float lo, float hi) {
    uint32_t r; asm("cvt.rn.f16x2.f32 %0, %1, %2;" : "=r"(r) : "f"(hi), "f"(lo)); return r;
}
static __device__ __forceinline__ void hmma16(float* c, const uint4 a, const uint2 b) {
    asm volatile("mma.sync.aligned.m16n8k16.row.col.f32.f16.f16.f32 "
                 "{%0,%1,%2,%3}, {%4,%5,%6,%7}, {%8,%9}, {%0,%1,%2,%3};"
                 : "+f"(c[0]), "+f"(c[1]), "+f"(c[2]), "+f"(c[3])
                 : "r"(a.x), "r"(a.y), "r"(a.z), "r"(a.w), "r"(b.x), "r"(b.y));
}
static __device__ __forceinline__ float tanha(float z) {
    float r; asm("tanh.approx.f32 %0, %1;" : "=f"(r) : "f"(z)); return r;
}
static __device__ __forceinline__ uint32_t tanh2(uint32_t z) {
    uint32_t r; asm("tanh.approx.f16x2 %0, %1;" : "=r"(r) : "r"(z)); return r;
}
static __device__ __forceinline__ uint32_t hmul2u(uint32_t a, uint32_t b) {
    uint32_t r; asm("mul.rn.f16x2 %0, %1, %2;" : "=r"(r) : "r"(a), "r"(b)); return r;
}
static __device__ __forceinline__ float2 h22f2(uint32_t w) {
    __half2 h = *reinterpret_cast<__half2*>(&w);
    return __half22float2(h);
}
// accurate versions (final output only)
static __device__ __forceinline__ float sigf(float z) {
    return __fdividef(1.f, 1.f + __expf(-z));
}
static __device__ __forceinline__ float tanhf2(float z) {
    return 2.f * sigf(2.f * z) - 1.f;
}
#define BAR_GRP(id) asm volatile("bar.sync %0, 256;" :: "r"(id) : "memory")

// ---------------- kernel 1: per-channel sum / sumsq (deterministic) --------
__global__ void k_stats(const float* __restrict__ x) {
    const int tid = threadIdx.x, bid = blockIdx.x;
    const float4* x4 = (const float4*)x;
    const int n4 = BB * TT * CC / 4;
    float4 s = make_float4(0.f, 0.f, 0.f, 0.f);
    float4 q = make_float4(0.f, 0.f, 0.f, 0.f);
    for (int i = bid * STAT_THREADS + tid; i < n4; i += NSTAT_BLK * STAT_THREADS) {
        float4 v = x4[i];
        s.x += v.x; s.y += v.y; s.z += v.z; s.w += v.w;
        q.x += v.x * v.x; q.y += v.y * v.y; q.z += v.z * v.z; q.w += v.w * v.w;
    }
    __shared__ float sm[STAT_THREADS][8];
    sm[tid][0] = s.x; sm[tid][1] = s.y; sm[tid][2] = s.z; sm[tid][3] = s.w;
    sm[tid][4] = q.x; sm[tid][5] = q.y; sm[tid][6] = q.z; sm[tid][7] = q.w;
    __syncthreads();
    for (int st = STAT_THREADS / 2; st >= 4; st >>= 1) {
        if (tid < st) {
#pragma unroll
            for (int w = 0; w < 8; w++) sm[tid][w] += sm[tid + st][w];
        }
        __syncthreads();
    }
    if (tid < 4) {
#pragma unroll
        for (int w = 0; w < 8; w++) g_part[bid * 32 + tid * 8 + w] = sm[tid][w];
    }
}

// ---------------- kernel 2: finalize stats, fold BN, build fp16 frags ------
__global__ void k_prep(const float* __restrict__ gamma, const float* __restrict__ beta,
                       const float* __restrict__ W_ih, const float* __restrict__ W_hh,
                       const float* __restrict__ b_ih, const float* __restrict__ b_hh) {
    __shared__ float red[32];
    __shared__ float scale[CC], shift[CC];
    const int tid = threadIdx.x;
    if (tid < 32) {
        float a = 0.f;
        for (int b = 0; b < NSTAT_BLK; b++) a += g_part[b * 32 + tid];
        red[tid] = a;
    }
    __syncthreads();
    if (tid < CC) {
        const int cg = tid >> 2, qq = tid & 3;
        const float n = (float)(BB * TT);
        const float sum = red[cg * 8 + qq];
        const float ssq = red[cg * 8 + 4 + qq];
        const float mean = sum / n;
        const float var = ssq / n - mean * mean;
        const float sc = gamma[tid] * rsqrtf(var + 1e-5f);
        scale[tid] = sc;
        shift[tid] = beta[tid] - mean * sc;
    }
    __syncthreads();

    for (int n = tid; n < GG; n += blockDim.x) {
        const int grow = (n & 3) * HH + (n >> 2);
        float bsum = b_ih[grow] + b_hh[grow];
#pragma unroll
        for (int c = 0; c < CC; c++) bsum += W_ih[grow * CC + c] * shift[c];
        g_bias_n[n] = bsum;
    }

    for (int idx = tid; idx < 56 * KT_H * 32; idx += blockDim.x) {
        const int nt = idx / (KT_H * 32);
        const int kt = (idx / 32) % KT_H;
        const int l = idx & 31;
        const int n = nt * 8 + (l >> 2);
        const int grow = (n & 3) * HH + (n >> 2);
        const int k0 = kt * 16 + 2 * (l & 3);
        g_Wfrag_h[idx] = make_uint2(
            pkh(W_hh[grow * HH + k0], W_hh[grow * HH + k0 + 1]),
            pkh(W_hh[grow * HH + k0 + 8], W_hh[grow * HH + k0 + 9]));
    }
    for (int idx = tid; idx < 56 * 32; idx += blockDim.x) {
        const int nt = idx / 32;
        const int l = idx & 31;
        const int n = nt * 8 + (l >> 2);
        const int grow = (n & 3) * HH + (n >> 2);
        const int k0 = 2 * (l & 3);
        g_Wfrag_x[idx] = make_uint2(
            pkh(W_ih[grow * CC + k0] * scale[k0], W_ih[grow * CC + k0 + 1] * scale[k0 + 1]),
            pkh(W_ih[grow * CC + k0 + 8] * scale[k0 + 8],
                W_ih[grow * CC + k0 + 9] * scale[k0 + 9]));
    }
}

// ---------------- kernel 3: persistent fp16 tensor-core LSTM ---------------
// smem: WfragS (100,352 B) + AfragS double-buffered (2 x 7,168 B)
// The two m-tile halves (warps 0-7 / 8-15) are fully independent through the
// recurrence: they sync on named barriers 1/2 and drift out of phase, so one
// half's MUFU epilogue overlaps the other's HMMA burst.
__global__ void __launch_bounds__(TPB, 1)
k_lstm(const float* __restrict__ x, const float* __restrict__ W_fc,
       const float* __restrict__ b_fc, float* __restrict__ out) {
    extern __shared__ __align__(16) char smem[];
    uint2* WfragS = (uint2*)smem;                           // 56*7*32 uint2
    uint32_t* AfragS = (uint32_t*)(smem + 56 * KT_H * 256); // 2 buffers x 1792 words
    float* Pfc = (float*)AfragS;                            // reused for FC partials

    const int tid = threadIdx.x;
    const int w = tid >> 5;
    const int wm = w >> 3;
    const int wn = w & 7;
    const int lane = tid & 31;
    const int q = lane & 3;
    const int rr = lane >> 2;
    const int b0 = blockIdx.x * MB;
    const int barid = 1 + wm;

    {
        const uint4* src = (const uint4*)g_Wfrag_h;
        uint4* dst = (uint4*)WfragS;
        for (int i = tid; i < 56 * KT_H * 16; i += TPB) dst[i] = src[i];
    }
    for (int i = tid; i < ABUF; i += TPB) AfragS[i] = 0u;

    uint2 bx[7];
#pragma unroll
    for (int i = 0; i < 7; i++) bx[i] = g_Wfrag_x[(wn * 7 + i) * 32 + lane];

    float bias0[7], bias1[7];
#pragma unroll
    for (int i = 0; i < 7; i++) {
        const int n = (wn * 7 + i) * 8 + 2 * q;
        bias0[i] = g_bias_n[n];
        bias1[i] = g_bias_n[n + 1];
    }

    const size_t xrow0 = (size_t)(b0 + wm * 16 + rr) * (TT * CC);
    const size_t xrow1 = (size_t)(b0 + wm * 16 + rr + 8) * (TT * CC);
    float2 xl0, xh0, xl1, xh1;
    {
        const float2* p0 = (const float2*)&x[xrow0 + 2 * q];
        const float2* p1 = (const float2*)&x[xrow1 + 2 * q];
        xl0 = __ldg(p0); xh0 = __ldg(p0 + 4);
        xl1 = __ldg(p1); xh1 = __ldg(p1 + 4);
    }

    float cc[7];
#pragma unroll
    for (int i = 0; i < 7; i++) cc[i] = 0.f;
    const bool evenq = (q & 1) == 0;
    // sigmoid-arg scaling folded at pack time: even lanes (zi,zf) -> {.5,.5};
    // odd lanes (zg,zo) -> {1.,.5}
    const uint32_t mulc = evenq ? pkh(0.5f, 0.5f) : pkh(1.0f, 0.5f);
    float hlast[7];

    __syncthreads();   // staging + A zero visible to both halves

    for (int t = 0; t < TT; t++) {
        const uint32_t* Ar = AfragS + (t & 1) * ABUF;
        uint32_t* Aw = AfragS + ((t + 1) & 1) * ABUF;

        float c[7][4];
#pragma unroll
        for (int i = 0; i < 7; i++) {
            c[i][0] = bias0[i]; c[i][1] = bias1[i];
            c[i][2] = bias0[i]; c[i][3] = bias1[i];
        }

        // ---- x part (register operands)
        {
            uint4 ax;
            ax.x = pkh(xl0.x, xl0.y);
            ax.y = pkh(xl1.x, xl1.y);
            ax.z = pkh(xh0.x, xh0.y);
            ax.w = pkh(xh1.x, xh1.y);
#pragma unroll
            for (int i = 0; i < 7; i++) hmma16(c[i], ax, bx[i]);
        }

        // ---- h part
#pragma unroll
        for (int kt = 0; kt < KT_H; kt++) {
            const uint4 a = *(const uint4*)&Ar[(wm * KT_H + kt) * 128 + lane * 4];
#pragma unroll
            for (int i = 0; i < 7; i++) {
                const uint2 b = WfragS[((wn * 7 + i) * KT_H + kt) * 32 + lane];
                hmma16(c[i], a, b);
            }
        }

        // prefetch x for t+1
        if (t + 1 < TT) {
            const float2* p0 = (const float2*)&x[xrow0 + (t + 1) * CC + 2 * q];
            const float2* p1 = (const float2*)&x[xrow1 + (t + 1) * CC + 2 * q];
            xl0 = __ldg(p0); xh0 = __ldg(p0 + 4);
            xl1 = __ldg(p1); xh1 = __ldg(p1 + 4);
        }

        BAR_GRP(barid);   // my half's reads of Ar (also the write target region of
                          // step t-1) are done; and Aw readers from t-1 are done

        // ---- epilogue: packed f16x2 gates
        const bool last = (t == TT - 1);
#pragma unroll
        for (int i = 0; i < 7; i++) {
            // pack both row-halves, scale sigmoid args, one packed tanh each
            uint32_t wL = tanh2(hmul2u(pkh(c[i][0], c[i][1]), mulc));  // row rr
            uint32_t wH = tanh2(hmul2u(pkh(c[i][2], c[i][3]), mulc));  // row rr+8
            const uint32_t send = evenq ? wH : wL;
            const uint32_t recv = __shfl_xor_sync(0xFFFFFFFF, send, 1);
            const float2 sf = h22f2(evenq ? wL : recv);   // (tanh(zi/2), tanh(zf/2))
            const float2 go = h22f2(evenq ? recv : wH);   // (tanh(zg), tanh(zo/2))
            const float ig = fmaf(sf.x, 0.5f, 0.5f);
            const float fg = fmaf(sf.y, 0.5f, 0.5f);
            const float gg = go.x;
            const float og = fmaf(go.y, 0.5f, 0.5f);
            const float cn = fg * cc[i] + ig * gg;
            cc[i] = cn;
            const float h = og * tanha(cn);
            if (last) {
                hlast[i] = h;
            } else {
                const float ho = __shfl_xor_sync(0xFFFFFFFF, h, 2);
                if (q < 2) {
                    const uint32_t hw = pkh(h, ho);
                    const int ntg = wn * 7 + i;
                    const int kt = ntg >> 3;
                    const int c8 = ntg & 7;
                    const int lane_r = rr * 4 + (c8 & 3);
                    const int e = q + 2 * (c8 >> 2);
                    Aw[(wm * KT_H + kt) * 128 + lane_r * 4 + e] = hw;
                }
            }
        }
        BAR_GRP(barid);   // h(t+1) frags visible to my half before next MMA
    }

    // ---- final FC (accurate tanh on output)
    __syncthreads();   // both halves done; Pfc aliases AfragS
    float p[6];
#pragma unroll
    for (int o = 0; o < 6; o++) p[o] = 0.f;
#pragma unroll
    for (int i = 0; i < 7; i++) {
        const int j = 2 * (wn * 7 + i) + (q >> 1);
        const float h = hlast[i];
#pragma unroll
        for (int o = 0; o < 6; o++) p[o] += h * __ldg(&W_fc[o * HH + j]);
    }
#pragma unroll
    for (int o = 0; o < 6; o++) p[o] += __shfl_xor_sync(0xFFFFFFFF, p[o], 2);
    if ((lane & 2) == 0) {
        const int row = wm * 16 + rr + (evenq ? 0 : 8);
#pragma unroll
        for (int o = 0; o < 6; o++) Pfc[(wn * MB + row) * 6 + o] = p[o];
    }
    __syncthreads();
    if (tid < MB * 6) {
        const int row = tid / 6, o = tid % 6;
        float s = b_fc[o];
#pragma unroll
        for (int w2 = 0; w2 < 8; w2++) s += Pfc[(w2 * MB + row) * 6 + o];
        out[(size_t)(b0 + row) * 6 + o] = tanhf2(s);
    }
}

// ---------------- launch ----------------------------------------------------
extern "C" void kernel_launch(void* const* d_in, const int* in_sizes, int n_in,
                              void* d_out, int out_size) {
    const float* x     = (const float*)d_in[0];
    const float* gamma = (const float*)d_in[1];
    const float* beta  = (const float*)d_in[2];
    const float* W_ih  = (const float*)d_in[3];
    const float* W_hh  = (const float*)d_in[4];
    const float* b_ih  = (const float*)d_in[5];
    const float* b_hh  = (const float*)d_in[6];
    const float* W_fc  = (const float*)d_in[7];
    const float* b_fc  = (const float*)d_in[8];
    float* out = (float*)d_out;

    const int smem_bytes = 56 * KT_H * 256 + 2 * ABUF * 4;  // 100352 + 14336 = 114688
    cudaFuncSetAttribute(k_lstm, cudaFuncAttributeMaxDynamicSharedMemorySize, smem_bytes);

    k_stats<<<NSTAT_BLK, STAT_THREADS>>>(x);
    k_prep<<<1, 512>>>(gamma, beta, W_ih, W_hh, b_ih, b_hh);
    k_lstm<<<NCTA, TPB, smem_bytes>>>(x, W_fc, b_fc, out);
}

// round 8
// speedup vs baseline: 1.0910x; 1.0910x over previous
#include <cuda_runtime.h>
#include <cuda_fp16.h>
#include <math.h>
#include <stdint.h>

#define BB 4096
#define TT 200
#define CC 16
#define HH 112
#define GG 448

#define NSTAT_BLK 256
#define STAT_THREADS 256

#define MB 32            // batch rows per CTA
#define TPB 512          // 16 warps: wm = warp>>3 (m-tile), wn = warp&7 (7 n-tiles)
#define NCTA (BB/MB)     // 128
#define KT_H 7           // k16-tiles for h (112)
#define ABUF (2 * KT_H * 128)   // words per A buffer (1792)

// ---------------- device scratch ----------------
__device__ float g_part[NSTAT_BLK * 32];
__device__ uint2 g_Wfrag_h[56 * KT_H * 32];   // 100,352 B
__device__ uint2 g_Wfrag_x[56 * 32];          // 14,336 B (BN-folded)
__device__ float g_bias_n[GG];                // bias per col n (n = j*4 + gate)

// ---------------- helpers ----------------
static __device__ __forceinline__ uint32_t pkh(float lo, float hi) {
    uint32_t r; asm("cvt.rn.f16x2.f32 %0, %1, %2;" : "=r"(r) : "f"(hi), "f"(lo)); return r;
}
static __device__ __forceinline__ void hmma16(float* c, const uint4 a, const uint2 b) {
    asm volatile("mma.sync.aligned.m16n8k16.row.col.f32.f16.f16.f32 "
                 "{%0,%1,%2,%3}, {%4,%5,%6,%7}, {%8,%9}, {%0,%1,%2,%3};"
                 : "+f"(c[0]), "+f"(c[1]), "+f"(c[2]), "+f"(c[3])
                 : "r"(a.x), "r"(a.y), "r"(a.z), "r"(a.w), "r"(b.x), "r"(b.y));
}
static __device__ __forceinline__ float tanha(float z) {
    float r; asm("tanh.approx.f32 %0, %1;" : "=f"(r) : "f"(z)); return r;
}
static __device__ __forceinline__ float siga(float z) {
    return fmaf(tanha(z * 0.5f), 0.5f, 0.5f);
}
// accurate versions (final output only)
static __device__ __forceinline__ float sigf(float z) {
    return __fdividef(1.f, 1.f + __expf(-z));
}
static __device__ __forceinline__ float tanhf2(float z) {
    return 2.f * sigf(2.f * z) - 1.f;
}
#define BAR_GRP(id) asm volatile("bar.sync %0, 256;" :: "r"(id) : "memory")

// ---------------- kernel 1: per-channel sum / sumsq (deterministic) --------
__global__ void k_stats(const float* __restrict__ x) {
    const int tid = threadIdx.x, bid = blockIdx.x;
    const float4* x4 = (const float4*)x;
    const int n4 = BB * TT * CC / 4;
    float4 s = make_float4(0.f, 0.f, 0.f, 0.f);
    float4 q = make_float4(0.f, 0.f, 0.f, 0.f);
    for (int i = bid * STAT_THREADS + tid; i < n4; i += NSTAT_BLK * STAT_THREADS) {
        float4 v = x4[i];
        s.x += v.x; s.y += v.y; s.z += v.z; s.w += v.w;
        q.x += v.x * v.x; q.y += v.y * v.y; q.z += v.z * v.z; q.w += v.w * v.w;
    }
    __shared__ float sm[STAT_THREADS][8];
    sm[tid][0] = s.x; sm[tid][1] = s.y; sm[tid][2] = s.z; sm[tid][3] = s.w;
    sm[tid][4] = q.x; sm[tid][5] = q.y; sm[tid][6] = q.z; sm[tid][7] = q.w;
    __syncthreads();
    for (int st = STAT_THREADS / 2; st >= 4; st >>= 1) {
        if (tid < st) {
#pragma unroll
            for (int w = 0; w < 8; w++) sm[tid][w] += sm[tid + st][w];
        }
        __syncthreads();
    }
    if (tid < 4) {
#pragma unroll
        for (int w = 0; w < 8; w++) g_part[bid * 32 + tid * 8 + w] = sm[tid][w];
    }
}

// ---------------- kernel 2: finalize stats, fold BN, build fp16 frags ------
__global__ void k_prep(const float* __restrict__ gamma, const float* __restrict__ beta,
                       const float* __restrict__ W_ih, const float* __restrict__ W_hh,
                       const float* __restrict__ b_ih, const float* __restrict__ b_hh) {
    __shared__ float red[32];
    __shared__ float scale[CC], shift[CC];
    const int tid = threadIdx.x;
    if (tid < 32) {
        float a = 0.f;
        for (int b = 0; b < NSTAT_BLK; b++) a += g_part[b * 32 + tid];
        red[tid] = a;
    }
    __syncthreads();
    if (tid < CC) {
        const int cg = tid >> 2, qq = tid & 3;
        const float n = (float)(BB * TT);
        const float sum = red[cg * 8 + qq];
        const float ssq = red[cg * 8 + 4 + qq];
        const float mean = sum / n;
        const float var = ssq / n - mean * mean;
        const float sc = gamma[tid] * rsqrtf(var + 1e-5f);
        scale[tid] = sc;
        shift[tid] = beta[tid] - mean * sc;
    }
    __syncthreads();

    for (int n = tid; n < GG; n += blockDim.x) {
        const int grow = (n & 3) * HH + (n >> 2);
        float bsum = b_ih[grow] + b_hh[grow];
#pragma unroll
        for (int c = 0; c < CC; c++) bsum += W_ih[grow * CC + c] * shift[c];
        g_bias_n[n] = bsum;
    }

    for (int idx = tid; idx < 56 * KT_H * 32; idx += blockDim.x) {
        const int nt = idx / (KT_H * 32);
        const int kt = (idx / 32) % KT_H;
        const int l = idx & 31;
        const int n = nt * 8 + (l >> 2);
        const int grow = (n & 3) * HH + (n >> 2);
        const int k0 = kt * 16 + 2 * (l & 3);
        g_Wfrag_h[idx] = make_uint2(
            pkh(W_hh[grow * HH + k0], W_hh[grow * HH + k0 + 1]),
            pkh(W_hh[grow * HH + k0 + 8], W_hh[grow * HH + k0 + 9]));
    }
    for (int idx = tid; idx < 56 * 32; idx += blockDim.x) {
        const int nt = idx / 32;
        const int l = idx & 31;
        const int n = nt * 8 + (l >> 2);
        const int grow = (n & 3) * HH + (n >> 2);
        const int k0 = 2 * (l & 3);
        g_Wfrag_x[idx] = make_uint2(
            pkh(W_ih[grow * CC + k0] * scale[k0], W_ih[grow * CC + k0 + 1] * scale[k0 + 1]),
            pkh(W_ih[grow * CC + k0 + 8] * scale[k0 + 8],
                W_ih[grow * CC + k0 + 9] * scale[k0 + 9]));
    }
}

// ---------------- kernel 3: persistent fp16 tensor-core LSTM ---------------
// Two independent m-tile halves on named barriers; half B is phase-skewed by
// ~100 dummy HMMAs so its MMA bursts overlap half A's epilogues (anti-phase).
__global__ void __launch_bounds__(TPB, 1)
k_lstm(const float* __restrict__ x, const float* __restrict__ W_fc,
       const float* __restrict__ b_fc, float* __restrict__ out) {
    extern __shared__ __align__(16) char smem[];
    uint2* WfragS = (uint2*)smem;                           // 56*7*32 uint2
    uint32_t* AfragS = (uint32_t*)(smem + 56 * KT_H * 256); // 2 buffers x 1792 words
    float* Pfc = (float*)AfragS;                            // reused for FC partials

    const int tid = threadIdx.x;
    const int w = tid >> 5;
    const int wm = w >> 3;
    const int wn = w & 7;
    const int lane = tid & 31;
    const int q = lane & 3;
    const int rr = lane >> 2;
    const int b0 = blockIdx.x * MB;
    const int barid = 1 + wm;

    {
        const uint4* src = (const uint4*)g_Wfrag_h;
        uint4* dst = (uint4*)WfragS;
        for (int i = tid; i < 56 * KT_H * 16; i += TPB) dst[i] = src[i];
    }
    for (int i = tid; i < ABUF; i += TPB) AfragS[i] = 0u;

    uint2 bx[7];
#pragma unroll
    for (int i = 0; i < 7; i++) bx[i] = g_Wfrag_x[(wn * 7 + i) * 32 + lane];

    float bias0[7], bias1[7];
#pragma unroll
    for (int i = 0; i < 7; i++) {
        const int n = (wn * 7 + i) * 8 + 2 * q;
        bias0[i] = g_bias_n[n];
        bias1[i] = g_bias_n[n + 1];
    }

    const size_t xrow0 = (size_t)(b0 + wm * 16 + rr) * (TT * CC);
    const size_t xrow1 = (size_t)(b0 + wm * 16 + rr + 8) * (TT * CC);
    float2 xl0, xh0, xl1, xh1;
    {
        const float2* p0 = (const float2*)&x[xrow0 + 2 * q];
        const float2* p1 = (const float2*)&x[xrow1 + 2 * q];
        xl0 = __ldg(p0); xh0 = __ldg(p0 + 4);
        xl1 = __ldg(p1); xh1 = __ldg(p1 + 4);
    }

    float cc[7];
#pragma unroll
    for (int i = 0; i < 7; i++) cc[i] = 0.f;
    const bool evenq = (q & 1) == 0;
    float hlast[7];

    __syncthreads();   // staging + A zero visible to both halves

    // ---- phase skew: half B burns ~100 dummy HMMAs on the zeroed buffer ----
    if (wm == 1) {
        float d[4] = {0.f, 0.f, 0.f, 0.f};
#pragma unroll
        for (int rep = 0; rep < 2; rep++) {
#pragma unroll
            for (int kt = 0; kt < KT_H; kt++) {
                const uint4 a = *(const uint4*)&AfragS[(KT_H + kt) * 128 + lane * 4];
#pragma unroll
                for (int i = 0; i < 7; i++) {
                    const uint2 b = WfragS[((wn * 7 + i) * KT_H + kt) * 32 + lane];
                    hmma16(d, a, b);
                }
            }
        }
        asm volatile("" :: "f"(d[0]), "f"(d[1]), "f"(d[2]), "f"(d[3]));
    }

    for (int t = 0; t < TT; t++) {
        BAR_GRP(barid);   // my half's A(t) writes visible; Aw readers (t-1) done

        const uint32_t* Ar = AfragS + (t & 1) * ABUF;
        uint32_t* Aw = AfragS + ((t + 1) & 1) * ABUF;

        float c[7][4];
#pragma unroll
        for (int i = 0; i < 7; i++) {
            c[i][0] = bias0[i]; c[i][1] = bias1[i];
            c[i][2] = bias0[i]; c[i][3] = bias1[i];
        }

        // ---- x part (register operands)
        {
            uint4 ax;
            ax.x = pkh(xl0.x, xl0.y);
            ax.y = pkh(xl1.x, xl1.y);
            ax.z = pkh(xh0.x, xh0.y);
            ax.w = pkh(xh1.x, xh1.y);
#pragma unroll
            for (int i = 0; i < 7; i++) hmma16(c[i], ax, bx[i]);
        }

        // ---- h part
#pragma unroll
        for (int kt = 0; kt < KT_H; kt++) {
            const uint4 a = *(const uint4*)&Ar[(wm * KT_H + kt) * 128 + lane * 4];
#pragma unroll
            for (int i = 0; i < 7; i++) {
                const uint2 b = WfragS[((wn * 7 + i) * KT_H + kt) * 32 + lane];
                hmma16(c[i], a, b);
            }
        }

        // prefetch x for t+1
        if (t + 1 < TT) {
            const float2* p0 = (const float2*)&x[xrow0 + (t + 1) * CC + 2 * q];
            const float2* p1 = (const float2*)&x[xrow1 + (t + 1) * CC + 2 * q];
            xl0 = __ldg(p0); xh0 = __ldg(p0 + 4);
            xl1 = __ldg(p1); xh1 = __ldg(p1 + 4);
        }

        // ---- epilogue (fast MUFU.TANH gates, f32)
        const bool last = (t == TT - 1);
#pragma unroll
        for (int i = 0; i < 7; i++) {
            const float s0 = evenq ? c[i][2] : c[i][0];
            const float s1 = evenq ? c[i][3] : c[i][1];
            const float r0 = __shfl_xor_sync(0xFFFFFFFF, s0, 1);
            const float r1 = __shfl_xor_sync(0xFFFFFFFF, s1, 1);
            const float zi = evenq ? c[i][0] : r0;
            const float zf = evenq ? c[i][1] : r1;
            const float zg = evenq ? r0 : c[i][2];
            const float zo = evenq ? r1 : c[i][3];
            const float ig = siga(zi);
            const float fg = siga(zf);
            const float gg = tanha(zg);
            const float og = siga(zo);
            const float cn = fg * cc[i] + ig * gg;
            cc[i] = cn;
            const float h = og * tanha(cn);
            if (last) {
                hlast[i] = h;
            } else {
                const float ho = __shfl_xor_sync(0xFFFFFFFF, h, 2);
                if (q < 2) {
                    const uint32_t hw = pkh(h, ho);
                    const int ntg = wn * 7 + i;
                    const int kt = ntg >> 3;
                    const int c8 = ntg & 7;
                    const int lane_r = rr * 4 + (c8 & 3);
                    const int e = q + 2 * (c8 >> 2);
                    Aw[(wm * KT_H + kt) * 128 + lane_r * 4 + e] = hw;
                }
            }
        }
    }

    // ---- final FC (accurate tanh on output)
    __syncthreads();   // both halves done; Pfc aliases AfragS
    float p[6];
#pragma unroll
    for (int o = 0; o < 6; o++) p[o] = 0.f;
#pragma unroll
    for (int i = 0; i < 7; i++) {
        const int j = 2 * (wn * 7 + i) + (q >> 1);
        const float h = hlast[i];
#pragma unroll
        for (int o = 0; o < 6; o++) p[o] += h * __ldg(&W_fc[o * HH + j]);
    }
#pragma unroll
    for (int o = 0; o < 6; o++) p[o] += __shfl_xor_sync(0xFFFFFFFF, p[o], 2);
    if ((lane & 2) == 0) {
        const int row = wm * 16 + rr + (evenq ? 0 : 8);
#pragma unroll
        for (int o = 0; o < 6; o++) Pfc[(wn * MB + row) * 6 + o] = p[o];
    }
    __syncthreads();
    if (tid < MB * 6) {
        const int row = tid / 6, o = tid % 6;
        float s = b_fc[o];
#pragma unroll
        for (int w2 = 0; w2 < 8; w2++) s += Pfc[(w2 * MB + row) * 6 + o];
        out[(size_t)(b0 + row) * 6 + o] = tanhf2(s);
    }
}

// ---------------- launch ----------------------------------------------------
extern "C" void kernel_launch(void* const* d_in, const int* in_sizes, int n_in,
                              void* d_out, int out_size) {
    const float* x     = (const float*)d_in[0];
    const float* gamma = (const float*)d_in[1];
    const float* beta  = (const float*)d_in[2];
    const float* W_ih  = (const float*)d_in[3];
    const float* W_hh  = (const float*)d_in[4];
    const float* b_ih  = (const float*)d_in[5];
    const float* b_hh  = (const float*)d_in[6];
    const float* W_fc  = (const float*)d_in[7];
    const float* b_fc  = (const float*)d_in[8];
    float* out = (float*)d_out;

    const int smem_bytes = 56 * KT_H * 256 + 2 * ABUF * 4;  // 100352 + 14336 = 114688
    cudaFuncSetAttribute(k_lstm, cudaFuncAttributeMaxDynamicSharedMemorySize, smem_bytes);

    k_stats<<<NSTAT_BLK, STAT_THREADS>>>(x);
    k_prep<<<1, 512>>>(gamma, beta, W_ih, W_hh, b_ih, b_hh);
    k_lstm<<<NCTA, TPB, smem_bytes>>>(x, W_fc, b_fc, out);
}